// round 3
// baseline (speedup 1.0000x reference)
#include <cuda_runtime.h>
#include <cstdint>
#include <math.h>

#define BB 256
#define TT 512
#define HH 256
#define EE 6
#define VV 10
#define CC 10

#define CLUSTER 8
#define NB 16            // batch columns per cluster
#define ROWS 32          // h-rows per CTA
#define SR 128           // stacked gate rows per CTA (4 gates * 32)
#define THREADS 256

#define WPAD 129
#define HPAD 20          // 80 B/row: keeps 16B alignment for ld.shared.v2.b64
#define PPAD 17
#define CPAD 17
#define TPAD 13

struct __align__(16) Smem {
    float W[HH][WPAD];        // W[k][sr] = Wh_gate[rowBase+lr][k]  (132096 B)
    float Hb[2][HH][HPAD];    // full h, double buffered, [k][col]  (40960 B)
    float Pre[SR][PPAD];      // gate pre-activations                (8704 B)
    float Cc[ROWS][CPAD];     // c state for own rows                (2176 B)
    float Tab[SR][TPAD];      // Wx@emb^T lookup per stacked row     (6656 B)
    float Bias[4][NB];
    int   dig[NB];
};

__device__ __forceinline__ void cluster_sync_() {
    asm volatile("barrier.cluster.arrive.aligned;" ::: "memory");
    asm volatile("barrier.cluster.wait.aligned;" ::: "memory");
}

__device__ __forceinline__ float sigmoidf_(float x) {
    return 1.0f / (1.0f + expf(-x));
}

__global__ void __cluster_dims__(CLUSTER, 1, 1) __launch_bounds__(THREADS, 1)
lstm_persistent_kernel(
    const int* __restrict__ x,   const float* __restrict__ emb,
    const float* __restrict__ Wxg, const float* __restrict__ Whg, const float* __restrict__ bg,
    const float* __restrict__ Wxi, const float* __restrict__ Whi, const float* __restrict__ bi,
    const float* __restrict__ Wxf, const float* __restrict__ Whf, const float* __restrict__ bf,
    const float* __restrict__ Wxo, const float* __restrict__ Who, const float* __restrict__ bo,
    const float* __restrict__ Wp,  const float* __restrict__ bp,
    float* __restrict__ out)
{
    extern __shared__ __align__(16) unsigned char smem_raw[];
    Smem& s = *reinterpret_cast<Smem*>(smem_raw);

    const int tid = threadIdx.x;
    uint32_t rank;
    asm("mov.u32 %0, %%cluster_ctarank;" : "=r"(rank));
    const int cluster = blockIdx.x / CLUSTER;
    const int colBase = cluster * NB;
    const int rowBase = (int)rank * ROWS;

    const float* WhArr[4] = {Whg, Whi, Whf, Who};
    const float* WxArr[4] = {Wxg, Wxi, Wxf, Wxo};
    const float* bArr[4]  = {bg,  bi,  bf,  bo};

    // ---------------- Prologue ----------------
    // Transposed weight load: s.W[k][sr] = Wh_gate[rowBase + lr][k]
    {
        const int warp = tid >> 5, lane = tid & 31;
        for (int sr = warp; sr < SR; sr += 8) {
            const int gate = sr >> 5, lr = sr & 31;
            const float* src = WhArr[gate] + (size_t)(rowBase + lr) * HH;
            #pragma unroll
            for (int k = lane; k < HH; k += 32)
                s.W[k][sr] = src[k];
        }
    }
    // Gate lookup tables: Tab[sr][d] = (Wx_gate @ emb^T)[row, d]
    for (int sr = tid; sr < SR; sr += THREADS) {
        const int gate = sr >> 5, lr = sr & 31;
        const float* wx = WxArr[gate] + (size_t)(rowBase + lr) * EE;
        #pragma unroll
        for (int d = 0; d < VV; d++) {
            float acc = 0.0f;
            #pragma unroll
            for (int e = 0; e < EE; e++) acc += wx[e] * emb[d * EE + e];
            s.Tab[sr][d] = acc;
        }
    }
    // Bias: reference semantics — (H,B) + (H,) broadcasts over the TRAILING
    // (batch) axis since H==B, so bias is indexed by BATCH column.
    if (tid < 4 * NB) {
        const int gate = tid / NB, c = tid % NB;
        s.Bias[gate][c] = bArr[gate][colBase + c];
    }
    // Zero h (both buffers) and c
    for (int i = tid; i < 2 * HH * HPAD; i += THREADS)
        reinterpret_cast<float*>(s.Hb)[i] = 0.0f;
    for (int i = tid; i < ROWS * CPAD; i += THREADS)
        reinterpret_cast<float*>(s.Cc)[i] = 0.0f;
    // Digits for t = 0
    if (tid < NB) s.dig[tid] = x[(size_t)(colBase + tid) * TT + 0];

    __syncthreads();
    cluster_sync_();   // peers' H buffers zeroed before any remote h writes

    const int sr   = tid & (SR - 1);   // stacked gate row this thread owns
    const int ch   = tid >> 7;         // column half (0/1)
    const int c0   = ch * 8;
    const int gate = sr >> 5;

    const uint32_t hbase0 = (uint32_t)__cvta_generic_to_shared(&s.Hb[0][0][c0]);
    const uint32_t hbase1 = (uint32_t)__cvta_generic_to_shared(&s.Hb[1][0][c0]);

    int cur = 0;

    for (int t = 0; t < TT; t++) {
        // --- accumulator init: x-path (table) + bias, packed into f32x2 ---
        uint64_t acc01, acc23, acc45, acc67;
        {
            float a[8];
            #pragma unroll
            for (int j = 0; j < 8; j++)
                a[j] = s.Tab[sr][s.dig[c0 + j]] + s.Bias[gate][c0 + j];
            asm("mov.b64 %0, {%1, %2};" : "=l"(acc01) : "f"(a[0]), "f"(a[1]));
            asm("mov.b64 %0, {%1, %2};" : "=l"(acc23) : "f"(a[2]), "f"(a[3]));
            asm("mov.b64 %0, {%1, %2};" : "=l"(acc45) : "f"(a[4]), "f"(a[5]));
            asm("mov.b64 %0, {%1, %2};" : "=l"(acc67) : "f"(a[6]), "f"(a[7]));
        }

        // --- recurrent GEMM (packed f32x2): acc[c] += W[k][sr] * h[k][c] ---
        uint32_t haddr = cur ? hbase1 : hbase0;
        #pragma unroll 4
        for (int k = 0; k < HH; k++) {
            const float w = s.W[k][sr];
            uint64_t w2;
            asm("mov.b64 %0, {%1, %1};" : "=l"(w2) : "f"(w));
            uint64_t h01, h23, h45, h67;
            asm volatile("ld.shared.v2.b64 {%0, %1}, [%2];"
                         : "=l"(h01), "=l"(h23) : "r"(haddr));
            asm volatile("ld.shared.v2.b64 {%0, %1}, [%2];"
                         : "=l"(h45), "=l"(h67) : "r"(haddr + 16));
            asm("fma.rn.f32x2 %0, %1, %2, %0;" : "+l"(acc01) : "l"(w2), "l"(h01));
            asm("fma.rn.f32x2 %0, %1, %2, %0;" : "+l"(acc23) : "l"(w2), "l"(h23));
            asm("fma.rn.f32x2 %0, %1, %2, %0;" : "+l"(acc45) : "l"(w2), "l"(h45));
            asm("fma.rn.f32x2 %0, %1, %2, %0;" : "+l"(acc67) : "l"(w2), "l"(h67));
            haddr += HPAD * 4;
        }
        {
            float a0, a1;
            asm("mov.b64 {%0, %1}, %2;" : "=f"(a0), "=f"(a1) : "l"(acc01));
            s.Pre[sr][c0 + 0] = a0; s.Pre[sr][c0 + 1] = a1;
            asm("mov.b64 {%0, %1}, %2;" : "=f"(a0), "=f"(a1) : "l"(acc23));
            s.Pre[sr][c0 + 2] = a0; s.Pre[sr][c0 + 3] = a1;
            asm("mov.b64 {%0, %1}, %2;" : "=f"(a0), "=f"(a1) : "l"(acc45));
            s.Pre[sr][c0 + 4] = a0; s.Pre[sr][c0 + 5] = a1;
            asm("mov.b64 {%0, %1}, %2;" : "=f"(a0), "=f"(a1) : "l"(acc67));
            s.Pre[sr][c0 + 6] = a0; s.Pre[sr][c0 + 7] = a1;
        }
        __syncthreads();

        // --- epilogue: nonlinearity + state update + DSMEM h broadcast ---
        const int nxt = cur ^ 1;
        #pragma unroll
        for (int pp = 0; pp < 2; pp++) {
            const int p  = tid + pp * 256;
            const int hr = p & 31;
            const int c  = p >> 5;
            const float g  = tanhf(s.Pre[hr][c]);
            const float ig = sigmoidf_(s.Pre[32 + hr][c]);
            const float fg = sigmoidf_(s.Pre[64 + hr][c]);
            const float og = sigmoidf_(s.Pre[96 + hr][c]);
            const float cc = g * ig + s.Cc[hr][c] * fg;
            s.Cc[hr][c] = cc;
            const float hh = tanhf(cc) * og;

            uint32_t laddr = (uint32_t)__cvta_generic_to_shared(&s.Hb[nxt][rowBase + hr][c]);
            #pragma unroll
            for (int r = 0; r < CLUSTER; r++) {
                uint32_t raddr;
                asm("mapa.shared::cluster.u32 %0, %1, %2;" : "=r"(raddr) : "r"(laddr), "r"(r));
                asm volatile("st.shared::cluster.f32 [%0], %1;" :: "r"(raddr), "f"(hh) : "memory");
            }
        }
        // Prefetch next step's digits (consumed only after the barrier)
        if (t + 1 < TT && tid < NB)
            s.dig[tid] = x[(size_t)(colBase + tid) * TT + (t + 1)];

        cluster_sync_();   // remote h writes visible cluster-wide
        cur ^= 1;
    }

    // -------- Final projection: out[b][j] = Wp[j,:] . h[:,b] + bp[j] --------
    if (tid < 2 * CC) {
        const int lc = 2 * (int)rank + tid / CC;   // this CTA owns 2 local columns
        const int j  = tid % CC;
        float acc = bp[j];
        const float* wp = Wp + (size_t)j * HH;
        #pragma unroll 4
        for (int r = 0; r < HH; r++)
            acc = fmaf(wp[r], s.Hb[cur][r][lc], acc);
        out[(size_t)(colBase + lc) * CC + j] = acc;
    }
}

extern "C" void kernel_launch(void* const* d_in, const int* in_sizes, int n_in,
                              void* d_out, int out_size) {
    const int*   x   = (const int*)  d_in[0];
    const float* emb = (const float*)d_in[1];
    const float* Wxg = (const float*)d_in[2];
    const float* Whg = (const float*)d_in[3];
    const float* bg  = (const float*)d_in[4];
    const float* Wxi = (const float*)d_in[5];
    const float* Whi = (const float*)d_in[6];
    const float* bi  = (const float*)d_in[7];
    const float* Wxf = (const float*)d_in[8];
    const float* Whf = (const float*)d_in[9];
    const float* bf  = (const float*)d_in[10];
    const float* Wxo = (const float*)d_in[11];
    const float* Who = (const float*)d_in[12];
    const float* bo  = (const float*)d_in[13];
    const float* Wp  = (const float*)d_in[14];
    const float* bp  = (const float*)d_in[15];
    float* out = (float*)d_out;

    cudaFuncSetAttribute(lstm_persistent_kernel,
                         cudaFuncAttributeMaxDynamicSharedMemorySize,
                         (int)sizeof(Smem));

    lstm_persistent_kernel<<<128, THREADS, sizeof(Smem)>>>(
        x, emb, Wxg, Whg, bg, Wxi, Whi, bi, Wxf, Whf, bf, Wxo, Who, bo, Wp, bp, out);
}

// round 4
// speedup vs baseline: 1.2504x; 1.2504x over previous
#include <cuda_runtime.h>
#include <cstdint>
#include <math.h>

#define BB 256
#define TT 512
#define HH 256
#define EE 6
#define VV 10
#define CC 10

#define CLUSTER 8
#define NB 16            // batch columns per cluster
#define ROWS 32          // h-rows per CTA
#define SR 128           // stacked gate rows per CTA (4 gates * 32)
#define THREADS 512      // 16 warps: sr(128) x k-quarter(4)
#define KQ 4
#define KPQ 32           // k-pairs per quarter (256 k / 2 / 4)

#define PADC 18          // Hp col-pairs per row (16 used + 2 pad); row=144B, 16B-aligned
#define PPAD 17
#define CPAD 17
#define TPAD 13

typedef unsigned long long ull;

struct __align__(16) Smem {
    float Wp2[128][128][2];    // [kp][sr][parity] = Wh row (rowBase+lr), k=2kp+par (131072 B)
    float Hp[2][128][PADC][2]; // [buf][kp][col][parity] = h[2kp+par][col]      (36864 B)
    float Pre[KQ][SR][PPAD];   // per-k-quarter partial pre-activations          (34816 B)
    float Cc[ROWS][CPAD];      // c state                                         (2176 B)
    float Tab[SR][TPAD];       // (Wx @ emb^T)[stacked row][digit]                (6656 B)
    float Bias[4][NB];
    int   dig[2][NB];
};

#define FMA2(a, b, c) asm("fma.rn.f32x2 %0, %1, %2, %0;" : "+l"(a) : "l"(b), "l"(c))

__device__ __forceinline__ void cluster_sync_() {
    asm volatile("barrier.cluster.arrive.aligned;" ::: "memory");
    asm volatile("barrier.cluster.wait.aligned;" ::: "memory");
}

__device__ __forceinline__ float sigmoidf_(float x) {
    return 1.0f / (1.0f + expf(-x));
}

__global__ void __cluster_dims__(CLUSTER, 1, 1) __launch_bounds__(THREADS, 1)
lstm_persistent_kernel(
    const int* __restrict__ x,   const float* __restrict__ emb,
    const float* __restrict__ Wxg, const float* __restrict__ Whg, const float* __restrict__ bg,
    const float* __restrict__ Wxi, const float* __restrict__ Whi, const float* __restrict__ bi,
    const float* __restrict__ Wxf, const float* __restrict__ Whf, const float* __restrict__ bf,
    const float* __restrict__ Wxo, const float* __restrict__ Who, const float* __restrict__ bo,
    const float* __restrict__ Wp,  const float* __restrict__ bp,
    float* __restrict__ out)
{
    extern __shared__ __align__(16) unsigned char smem_raw[];
    Smem& s = *reinterpret_cast<Smem*>(smem_raw);

    const int tid = threadIdx.x;
    uint32_t rank;
    asm("mov.u32 %0, %%cluster_ctarank;" : "=r"(rank));
    const int cluster = blockIdx.x / CLUSTER;
    const int colBase = cluster * NB;
    const int rowBase = (int)rank * ROWS;

    const float* WhArr[4] = {Whg, Whi, Whf, Who};
    const float* WxArr[4] = {Wxg, Wxi, Wxf, Wxo};
    const float* bArr[4]  = {bg,  bi,  bf,  bo};

    // ---------------- Prologue ----------------
    {
        const int warp = tid >> 5, lane = tid & 31;
        // k-paired transposed weights: Wp2[k>>1][sr][k&1] = Wh_gate[rowBase+lr][k]
        for (int sr = warp; sr < SR; sr += 16) {
            const int gate = sr >> 5, lr = sr & 31;
            const float* src = WhArr[gate] + (size_t)(rowBase + lr) * HH;
            #pragma unroll
            for (int k = lane; k < HH; k += 32)
                s.Wp2[k >> 1][sr][k & 1] = src[k];
        }
    }
    // Gate digit tables: Tab[sr][d] = (Wx_gate @ emb^T)[row, d]
    for (int sr = tid; sr < SR; sr += THREADS) {
        const int gate = sr >> 5, lr = sr & 31;
        const float* wx = WxArr[gate] + (size_t)(rowBase + lr) * EE;
        #pragma unroll
        for (int d = 0; d < VV; d++) {
            float acc = 0.0f;
            #pragma unroll
            for (int e = 0; e < EE; e++) acc += wx[e] * emb[d * EE + e];
            s.Tab[sr][d] = acc;
        }
    }
    // Reference semantics: (H,B) + (H,) broadcasts over trailing (batch) axis
    // since H==B, so bias is indexed by BATCH column.
    if (tid < 4 * NB) {
        const int gate = tid / NB, c = tid % NB;
        s.Bias[gate][c] = bArr[gate][colBase + c];
    }
    // Zero h (both buffers) and c
    for (int i = tid; i < 2 * 128 * PADC * 2; i += THREADS)
        reinterpret_cast<float*>(s.Hp)[i] = 0.0f;
    for (int i = tid; i < ROWS * CPAD; i += THREADS)
        reinterpret_cast<float*>(s.Cc)[i] = 0.0f;
    if (tid < NB) s.dig[0][tid] = x[(size_t)(colBase + tid) * TT + 0];

    __syncthreads();
    cluster_sync_();   // peers' Hp zeroed before any remote h writes

    const int sr  = tid & (SR - 1);    // stacked gate row
    const int kq  = tid >> 7;          // k-quarter (0..3)
    const int kp0 = kq * KPQ;

    const int hr = tid & 31;           // epilogue: own h row
    const int ec = tid >> 5;           // epilogue: own column (0..15)

    int cur = 0;

    for (int t = 0; t < TT; t++) {
        // ---- recurrent GEMM, k-paired f32x2: acc[c] = {sum_even, sum_odd} ----
        ull acc[16];
        #pragma unroll
        for (int c = 0; c < 16; c++) acc[c] = 0ULL;

        const float* __restrict__ hq = &s.Hp[cur][kp0][0][0];
        const float* __restrict__ wq = &s.Wp2[kp0][0][0];
        #pragma unroll 4
        for (int kp = 0; kp < KPQ; kp++) {
            const ull w2 = *reinterpret_cast<const ull*>(wq + kp * 256 + sr * 2);
            const float* hrow = hq + kp * (PADC * 2);
            #pragma unroll
            for (int cg = 0; cg < 4; cg++) {
                const ulonglong2 hA = *reinterpret_cast<const ulonglong2*>(hrow + cg * 8);
                FMA2(acc[cg * 4 + 0], w2, hA.x);
                FMA2(acc[cg * 4 + 1], w2, hA.y);
                const ulonglong2 hB = *reinterpret_cast<const ulonglong2*>(hrow + cg * 8 + 4);
                FMA2(acc[cg * 4 + 2], w2, hB.x);
                FMA2(acc[cg * 4 + 3], w2, hB.y);
            }
        }
        // horizontal (even+odd) add, store partial
        #pragma unroll
        for (int c = 0; c < 16; c++) {
            const float2 p = *reinterpret_cast<const float2*>(&acc[c]);
            s.Pre[kq][sr][c] = p.x + p.y;
        }
        __syncthreads();

        // ---- epilogue: one h value per thread ----
        const int d = s.dig[t & 1][ec];
        float pre[4];
        #pragma unroll
        for (int g = 0; g < 4; g++) {
            const int gr = g * 32 + hr;
            pre[g] = s.Pre[0][gr][ec] + s.Pre[1][gr][ec]
                   + s.Pre[2][gr][ec] + s.Pre[3][gr][ec]
                   + s.Tab[gr][d] + s.Bias[g][ec];
        }
        const float gg = tanhf(pre[0]);
        const float ii = sigmoidf_(pre[1]);
        const float ff = sigmoidf_(pre[2]);
        const float oo = sigmoidf_(pre[3]);
        const float cc = gg * ii + s.Cc[hr][ec] * ff;
        s.Cc[hr][ec] = cc;
        const float hh = tanhf(cc) * oo;

        const int nxt = cur ^ 1;
        uint32_t laddr = (uint32_t)__cvta_generic_to_shared(
            &s.Hp[nxt][(int)rank * 16 + (hr >> 1)][ec][hr & 1]);
        #pragma unroll
        for (int r = 0; r < CLUSTER; r++) {
            uint32_t raddr;
            asm("mapa.shared::cluster.u32 %0, %1, %2;" : "=r"(raddr) : "r"(laddr), "r"(r));
            asm volatile("st.shared::cluster.f32 [%0], %1;" :: "r"(raddr), "f"(hh) : "memory");
        }

        // prefetch next step's digits into the other buffer
        if (t + 1 < TT && tid < NB)
            s.dig[(t + 1) & 1][tid] = x[(size_t)(colBase + tid) * TT + (t + 1)];

        cluster_sync_();   // remote h writes visible cluster-wide
        cur ^= 1;
    }

    // -------- Final projection: out[b][j] = Wp[j,:] . h[:,b] + bp[j] --------
    if (tid < 2 * CC) {
        const int lc = 2 * (int)rank + tid / CC;   // this CTA owns 2 cluster columns
        const int j  = tid % CC;
        float acc = bp[j];
        const float* wp = Wp + (size_t)j * HH;
        #pragma unroll 4
        for (int r = 0; r < HH; r++)
            acc = fmaf(wp[r], s.Hp[cur][r >> 1][lc][r & 1], acc);
        out[(size_t)(colBase + lc) * CC + j] = acc;
    }
}

extern "C" void kernel_launch(void* const* d_in, const int* in_sizes, int n_in,
                              void* d_out, int out_size) {
    const int*   x   = (const int*)  d_in[0];
    const float* emb = (const float*)d_in[1];
    const float* Wxg = (const float*)d_in[2];
    const float* Whg = (const float*)d_in[3];
    const float* bg  = (const float*)d_in[4];
    const float* Wxi = (const float*)d_in[5];
    const float* Whi = (const float*)d_in[6];
    const float* bi  = (const float*)d_in[7];
    const float* Wxf = (const float*)d_in[8];
    const float* Whf = (const float*)d_in[9];
    const float* bf  = (const float*)d_in[10];
    const float* Wxo = (const float*)d_in[11];
    const float* Who = (const float*)d_in[12];
    const float* bo  = (const float*)d_in[13];
    const float* Wp  = (const float*)d_in[14];
    const float* bp  = (const float*)d_in[15];
    float* out = (float*)d_out;

    cudaFuncSetAttribute(lstm_persistent_kernel,
                         cudaFuncAttributeMaxDynamicSharedMemorySize,
                         (int)sizeof(Smem));

    lstm_persistent_kernel<<<128, THREADS, sizeof(Smem)>>>(
        x, emb, Wxg, Whg, bg, Wxi, Whi, bi, Wxf, Whf, bf, Wxo, Who, bo, Wp, bp, out);
}

// round 5
// speedup vs baseline: 1.5246x; 1.2193x over previous
#include <cuda_runtime.h>
#include <cstdint>
#include <math.h>

#define BB 256
#define TT 512
#define HH 256
#define EE 6
#define VV 10
#define CC 10

#define CLUSTER 8
#define NB 16            // batch columns per cluster
#define ROWS 32          // h-rows per CTA
#define SR 128           // stacked gate rows per CTA (4 gates * 32)
#define THREADS 512      // 16 warps: sr(128) x k-quarter(4)
#define KQ 4

#define SRP 132          // padded sr dimension (128 used)
#define KPP 132          // padded kp dimension (128 used)

typedef unsigned long long ull;

struct __align__(16) Smem {
    float Wp4[64][128][4];       // [k>>2][sr][k&3] = Wh_gate[rowBase+lr][k]   (131072 B)
    float Hp[2][NB][KPP][2];     // [buf][col][kp][par] = h[2kp+par][col]      (33792 B)
    float Pre[KQ][NB][SRP];      // [kq][col][sr] partial pre-activations      (33792 B)
    float Cc[NB][ROWS];          // [col][hr] c-state                           (2048 B)
    float Tab[VV][SRP];          // [digit][sr] = (Wx@emb^T)[sr][digit]         (5280 B)
    float Bias[4][NB];
    unsigned char dig8[NB][TT];  // all digits preloaded                        (8192 B)
};

#define FMA2(a, b, c) asm("fma.rn.f32x2 %0, %1, %2, %0;" : "+l"(a) : "l"(b), "l"(c))

__device__ __forceinline__ void cluster_sync_() {
    asm volatile("barrier.cluster.arrive.aligned;" ::: "memory");
    asm volatile("barrier.cluster.wait.aligned;" ::: "memory");
}

__device__ __forceinline__ float fast_sigmoid(float x) {
    return __fdividef(1.0f, 1.0f + __expf(-x));
}
__device__ __forceinline__ float fast_tanh(float x) {
    return 1.0f - __fdividef(2.0f, __expf(2.0f * x) + 1.0f);
}

__global__ void __cluster_dims__(CLUSTER, 1, 1) __launch_bounds__(THREADS, 1)
lstm_persistent_kernel(
    const int* __restrict__ x,   const float* __restrict__ emb,
    const float* __restrict__ Wxg, const float* __restrict__ Whg, const float* __restrict__ bg,
    const float* __restrict__ Wxi, const float* __restrict__ Whi, const float* __restrict__ bi,
    const float* __restrict__ Wxf, const float* __restrict__ Whf, const float* __restrict__ bf,
    const float* __restrict__ Wxo, const float* __restrict__ Who, const float* __restrict__ bo,
    const float* __restrict__ Wp,  const float* __restrict__ bp,
    float* __restrict__ out)
{
    extern __shared__ __align__(16) unsigned char smem_raw[];
    Smem& s = *reinterpret_cast<Smem*>(smem_raw);

    const int tid = threadIdx.x;
    uint32_t rank;
    asm("mov.u32 %0, %%cluster_ctarank;" : "=r"(rank));
    const int cluster = blockIdx.x / CLUSTER;
    const int colBase = cluster * NB;
    const int rowBase = (int)rank * ROWS;

    const float* WhArr[4] = {Whg, Whi, Whf, Who};
    const float* WxArr[4] = {Wxg, Wxi, Wxf, Wxo};
    const float* bArr[4]  = {bg,  bi,  bf,  bo};

    // ---------------- Prologue ----------------
    {
        const int warp = tid >> 5, lane = tid & 31;
        // k-quadded transposed weights: Wp4[k>>2][sr][k&3] = Wh_gate[rowBase+lr][k]
        for (int sr = warp; sr < SR; sr += 16) {
            const int gate = sr >> 5, lr = sr & 31;
            const float* src = WhArr[gate] + (size_t)(rowBase + lr) * HH;
            #pragma unroll
            for (int k = lane; k < HH; k += 32)
                s.Wp4[k >> 2][sr][k & 3] = src[k];
        }
    }
    // Gate digit tables (transposed): Tab[d][sr] = (Wx_gate @ emb^T)[row, d]
    for (int sr = tid; sr < SR; sr += THREADS) {
        const int gate = sr >> 5, lr = sr & 31;
        const float* wx = WxArr[gate] + (size_t)(rowBase + lr) * EE;
        #pragma unroll
        for (int d = 0; d < VV; d++) {
            float acc = 0.0f;
            #pragma unroll
            for (int e = 0; e < EE; e++) acc += wx[e] * emb[d * EE + e];
            s.Tab[d][sr] = acc;
        }
    }
    // Reference semantics: (H,B) + (H,) broadcasts over trailing (batch) axis
    // since H==B, so bias is indexed by BATCH column.
    if (tid < 4 * NB) {
        const int gate = tid / NB, c = tid % NB;
        s.Bias[gate][c] = bArr[gate][colBase + c];
    }
    // Zero h (both buffers) and c
    for (int i = tid; i < 2 * NB * KPP * 2; i += THREADS)
        reinterpret_cast<float*>(s.Hp)[i] = 0.0f;
    for (int i = tid; i < NB * ROWS; i += THREADS)
        reinterpret_cast<float*>(s.Cc)[i] = 0.0f;
    // Preload ALL digits as u8 (removes per-step global loads entirely)
    for (int i = tid; i < NB * TT; i += THREADS) {
        const int col = i >> 9, t = i & (TT - 1);
        s.dig8[col][t] = (unsigned char)x[(size_t)(colBase + col) * TT + t];
    }

    __syncthreads();
    cluster_sync_();   // peers' Hp zeroed before any remote h writes

    const int sr = tid & (SR - 1);     // stacked gate row (GEMM phase)
    const int kq = tid >> 7;           // k-quarter (0..3)

    const int hr = tid & 31;           // epilogue: own h row
    const int ec = tid >> 5;           // epilogue: own column (0..15)

    // Precompute the 8 remote DSMEM base addresses (mapa once, not per step)
    uint32_t rbase[CLUSTER];
    {
        uint32_t l0 = (uint32_t)__cvta_generic_to_shared(&s.Hp[0][0][0][0]);
        #pragma unroll
        for (int r = 0; r < CLUSTER; r++)
            asm("mapa.shared::cluster.u32 %0, %1, %2;" : "=r"(rbase[r]) : "r"(l0), "r"(r));
    }
    // byte offset within Hp for this thread's h pair store (per buffer)
    const uint32_t pairOff = (uint32_t)(ec * (KPP * 2 * 4) + ((int)rank * 16 + (hr >> 1)) * 8);
    const uint32_t bufStride = NB * KPP * 2 * 4;

    int cur = 0;

    for (int t = 0; t < TT; t++) {
        // ---- recurrent GEMM, k-paired f32x2 ----
        ull acc[NB];
        #pragma unroll
        for (int c = 0; c < NB; c++) acc[c] = 0ULL;

        const ulonglong2* __restrict__ wq =
            reinterpret_cast<const ulonglong2*>(&s.Wp4[kq * 16][sr][0]);
        const float* __restrict__ hbase = &s.Hp[cur][0][kq * 32][0];

        #pragma unroll 4
        for (int j = 0; j < 16; j++) {
            const ulonglong2 w = wq[(size_t)j * 128];      // Wp4[kq*16+j][sr][0..3]
            const float* hj = hbase + j * 4;               // kp = kq*32 + 2j
            #pragma unroll
            for (int c = 0; c < NB; c++) {
                const ulonglong2 h2 =
                    *reinterpret_cast<const ulonglong2*>(hj + c * (KPP * 2));
                FMA2(acc[c], w.x, h2.x);
                FMA2(acc[c], w.y, h2.y);
            }
        }
        // horizontal (even+odd) add, store partials lane-contiguously
        #pragma unroll
        for (int c = 0; c < NB; c++) {
            const float2 p = *reinterpret_cast<const float2*>(&acc[c]);
            s.Pre[kq][c][sr] = p.x + p.y;
        }
        __syncthreads();

        // ---- epilogue: one h value per thread, all accesses lane-contiguous ----
        const int d = s.dig8[ec][t];
        float pre[4];
        #pragma unroll
        for (int g = 0; g < 4; g++) {
            const int gr = g * 32 + hr;
            pre[g] = s.Pre[0][ec][gr] + s.Pre[1][ec][gr]
                   + s.Pre[2][ec][gr] + s.Pre[3][ec][gr]
                   + s.Tab[d][gr] + s.Bias[g][ec];
        }
        const float gg = fast_tanh(pre[0]);
        const float ii = fast_sigmoid(pre[1]);
        const float ff = fast_sigmoid(pre[2]);
        const float oo = fast_sigmoid(pre[3]);
        const float cc = gg * ii + s.Cc[ec][hr] * ff;
        s.Cc[ec][hr] = cc;
        const float hh = fast_tanh(cc) * oo;

        // pair (even,odd) rows into one 8B value, broadcast to all 8 CTAs
        const int nxt = cur ^ 1;
        const float hhOdd = __shfl_down_sync(0xffffffffu, hh, 1);
        if ((hr & 1) == 0) {
            ull hp;
            asm("mov.b64 %0, {%1, %2};" : "=l"(hp) : "f"(hh), "f"(hhOdd));
            const uint32_t off = pairOff + (uint32_t)nxt * bufStride;
            #pragma unroll
            for (int r = 0; r < CLUSTER; r++) {
                asm volatile("st.shared::cluster.b64 [%0], %1;"
                             :: "r"(rbase[r] + off), "l"(hp) : "memory");
            }
        }

        cluster_sync_();   // remote h writes visible cluster-wide
        cur ^= 1;
    }

    // -------- Final projection: out[b][j] = Wp[j,:] . h[:,b] + bp[j] --------
    if (tid < 2 * CC) {
        const int lc = 2 * (int)rank + tid / CC;   // this CTA owns 2 cluster columns
        const int j  = tid % CC;
        float acc = bp[j];
        const float* wp = Wp + (size_t)j * HH;
        #pragma unroll 4
        for (int r = 0; r < HH; r++)
            acc = fmaf(wp[r], s.Hp[cur][lc][r >> 1][r & 1], acc);
        out[(size_t)(colBase + lc) * CC + j] = acc;
    }
}

extern "C" void kernel_launch(void* const* d_in, const int* in_sizes, int n_in,
                              void* d_out, int out_size) {
    const int*   x   = (const int*)  d_in[0];
    const float* emb = (const float*)d_in[1];
    const float* Wxg = (const float*)d_in[2];
    const float* Whg = (const float*)d_in[3];
    const float* bg  = (const float*)d_in[4];
    const float* Wxi = (const float*)d_in[5];
    const float* Whi = (const float*)d_in[6];
    const float* bi  = (const float*)d_in[7];
    const float* Wxf = (const float*)d_in[8];
    const float* Whf = (const float*)d_in[9];
    const float* bf  = (const float*)d_in[10];
    const float* Wxo = (const float*)d_in[11];
    const float* Who = (const float*)d_in[12];
    const float* bo  = (const float*)d_in[13];
    const float* Wp  = (const float*)d_in[14];
    const float* bp  = (const float*)d_in[15];
    float* out = (float*)d_out;

    cudaFuncSetAttribute(lstm_persistent_kernel,
                         cudaFuncAttributeMaxDynamicSharedMemorySize,
                         (int)sizeof(Smem));

    lstm_persistent_kernel<<<128, THREADS, sizeof(Smem)>>>(
        x, emb, Wxg, Whg, bg, Wxi, Whi, bi, Wxf, Whf, bf, Wxo, Who, bo, Wp, bp, out);
}